// round 14
// baseline (speedup 1.0000x reference)
#include <cuda_runtime.h>
#include <cuda_pipeline.h>
#include <cstdint>
#include <math.h>

#define BB 2
#define SS 2049
#define SSP 2052
#define EE 512
#define HH 8
#define WINW 1024
#define MROWS (BB * SS)                  // 4098
#define SCALE 0.125f                     // D^-0.5
#define BIASC (-1.9073486328125e-6f)     // -0.5/(512^2)
#define LOG2E 1.4426950408889634f

// Scratch (device globals: no allocation allowed)
__device__ float g_q[MROWS * EE];        // column-permuted within 8-groups
__device__ float g_k[MROWS * EE];        // column-permuted within 8-groups
__device__ float g_vt[BB * HH * 64 * SSP]; // V transposed: [b][h][d][s]
__device__ float g_ao[MROWS * EE];
__device__ float g_gq[MROWS];
__device__ float g_gk[MROWS];

// ============================================================================
// helpers
// ============================================================================
__device__ __forceinline__ float tf32r(float x) {
    uint32_t u;
    asm("cvt.rna.tf32.f32 %0, %1;" : "=r"(u) : "f"(x));
    return __uint_as_float(u);
}
__device__ __forceinline__ void mma_tf32(float* d, const uint32_t* a, const uint32_t* b) {
    asm volatile(
        "mma.sync.aligned.m16n8k8.row.col.f32.tf32.tf32.f32 "
        "{%0,%1,%2,%3}, {%4,%5,%6,%7}, {%8,%9}, {%0,%1,%2,%3};"
        : "+f"(d[0]), "+f"(d[1]), "+f"(d[2]), "+f"(d[3])
        : "r"(a[0]), "r"(a[1]), "r"(a[2]), "r"(a[3]), "r"(b[0]), "r"(b[1]));
}
__device__ __forceinline__ float rcpf(float x) {
    float r;
    asm("rcp.approx.f32 %0, %1;" : "=f"(r) : "f"(x));
    return r;
}
__device__ __forceinline__ float ex2f(float x) {
    float r;
    asm("ex2.approx.f32 %0, %1;" : "=f"(r) : "f"(x));
    return r;
}
// within-8 permutation: original offset o -> stored position
__device__ __forceinline__ int perm8(int o) {
    return ((o & 3) << 1) | ((o >> 2) & 1);
}

// ---------------------------------------------------------------------------
// 1xTF32 GEMM body (rna-rounded at staging), software-pipelined
// double-buffered. BM=128 BN=128 BK=16, 256 thr, warp tile 32x64.
// MODE 0: normal row-major out; MODE 1: within-8 column-permuted out (Q,K);
// MODE 2: transposed out into g_vt (V).
// ---------------------------------------------------------------------------
#define GSTR 136
#define TILEF (16 * GSTR)
#define GEMM_SMEM (4 * TILEF * 4)

template <int MODE>
__device__ __forceinline__ void gemm_body(
    const float* __restrict__ A, const float* __restrict__ B,
    const float* __restrict__ bias, float* __restrict__ C, int M,
    int row0, int col0, float* sm)
{
    float* Ab = sm;
    float* Bb = sm + 2 * TILEF;

    const int tid = threadIdx.x;
    const int wid = tid >> 5, lane = tid & 31;
    const int g = lane >> 2, tg = lane & 3;
    const int wm = wid >> 1, wn = wid & 1;
    const int wrow = wm * 32, wcol = wn * 64;

    const int a_r0 = tid >> 2, a_c = (tid & 3) * 4;
    const int b_k0 = tid >> 5, b_c = (tid & 31) * 4;

    float acc[2][8][4];
#pragma unroll
    for (int mt = 0; mt < 2; mt++)
#pragma unroll
        for (int nt = 0; nt < 8; nt++)
#pragma unroll
            for (int e = 0; e < 4; e++) acc[mt][nt][e] = 0.f;

    float4 pa[2], pb[2];

#define G_LDG(K0)                                                              \
    {                                                                          \
        _Pragma("unroll")                                                      \
        for (int it = 0; it < 2; it++) {                                       \
            int r = a_r0 + it * 64;                                            \
            pa[it] = make_float4(0.f, 0.f, 0.f, 0.f);                          \
            if (row0 + r < M)                                                  \
                pa[it] = *(const float4*)&A[(size_t)(row0 + r) * 512 + (K0) + a_c]; \
            int kr = b_k0 + it * 8;                                            \
            pb[it] = *(const float4*)&B[(size_t)((K0) + kr) * 512 + col0 + b_c];    \
        }                                                                      \
    }

#define G_STS(Q)                                                               \
    {                                                                          \
        float* ab = Ab + (Q) * TILEF;                                          \
        float* bb = Bb + (Q) * TILEF;                                          \
        _Pragma("unroll")                                                      \
        for (int it = 0; it < 2; it++) {                                       \
            int r = a_r0 + it * 64;                                            \
            ab[(a_c + 0) * GSTR + r] = tf32r(pa[it].x);                        \
            ab[(a_c + 1) * GSTR + r] = tf32r(pa[it].y);                        \
            ab[(a_c + 2) * GSTR + r] = tf32r(pa[it].z);                        \
            ab[(a_c + 3) * GSTR + r] = tf32r(pa[it].w);                        \
            int kr = b_k0 + it * 8;                                            \
            float4 hv;                                                         \
            hv.x = tf32r(pb[it].x);                                            \
            hv.y = tf32r(pb[it].y);                                            \
            hv.z = tf32r(pb[it].z);                                            \
            hv.w = tf32r(pb[it].w);                                            \
            *(float4*)&bb[kr * GSTR + b_c] = hv;                               \
        }                                                                      \
    }

    G_LDG(0);
    G_STS(0);
    G_LDG(16);
    __syncthreads();

    int p = 0;
    for (int k0 = 0; k0 < 512; k0 += 16) {
        if (k0 + 16 < 512) {
            G_STS(1 - p);
            if (k0 + 32 < 512) G_LDG(k0 + 32);
        }

        const float* ab_ = Ab + p * TILEF;
        const float* bb_ = Bb + p * TILEF;
#pragma unroll
        for (int ks = 0; ks < 2; ks++) {
            const int kk = ks * 8;
            uint32_t af[2][4];
#pragma unroll
            for (int mt = 0; mt < 2; mt++) {
                int r = wrow + mt * 16;
                af[mt][0] = __float_as_uint(ab_[(kk + tg) * GSTR + r + g]);
                af[mt][1] = __float_as_uint(ab_[(kk + tg) * GSTR + r + g + 8]);
                af[mt][2] = __float_as_uint(ab_[(kk + tg + 4) * GSTR + r + g]);
                af[mt][3] = __float_as_uint(ab_[(kk + tg + 4) * GSTR + r + g + 8]);
            }
            uint32_t bf[8][2];
#pragma unroll
            for (int nt = 0; nt < 8; nt++) {
                int c = wcol + nt * 8;
                bf[nt][0] = __float_as_uint(bb_[(kk + tg) * GSTR + c + g]);
                bf[nt][1] = __float_as_uint(bb_[(kk + tg + 4) * GSTR + c + g]);
            }
#pragma unroll
            for (int mt = 0; mt < 2; mt++)
#pragma unroll
                for (int nt = 0; nt < 8; nt++)
                    mma_tf32(acc[mt][nt], af[mt], bf[nt]);
        }

        if (k0 + 16 < 512) {
            __syncthreads();
            p ^= 1;
        }
    }

#pragma unroll
    for (int mt = 0; mt < 2; mt++) {
        int r0 = row0 + wrow + mt * 16 + g;
#pragma unroll
        for (int nt = 0; nt < 8; nt++) {
            int c = col0 + wcol + nt * 8 + 2 * tg;
            float b0v = bias[c], b1v = bias[c + 1];
            float v00 = acc[mt][nt][0] + b0v, v01 = acc[mt][nt][1] + b1v;
            float v10 = acc[mt][nt][2] + b0v, v11 = acc[mt][nt][3] + b1v;
            if (MODE == 0) {
                if (r0 < M)
                    *(float2*)&C[(size_t)r0 * 512 + c] = make_float2(v00, v01);
                if (r0 + 8 < M)
                    *(float2*)&C[(size_t)(r0 + 8) * 512 + c] = make_float2(v10, v11);
            } else if (MODE == 1) {
                int c0p = (c & ~7) | perm8(c & 7);
                int c1p = (c & ~7) | perm8((c + 1) & 7);
                if (r0 < M) {
                    C[(size_t)r0 * 512 + c0p] = v00;
                    C[(size_t)r0 * 512 + c1p] = v01;
                }
                if (r0 + 8 < M) {
                    C[(size_t)(r0 + 8) * 512 + c0p] = v10;
                    C[(size_t)(r0 + 8) * 512 + c1p] = v11;
                }
            } else {
                int hh = c >> 6, d = c & 63;
                size_t base = ((size_t)hh * 64 + d) * SSP;   // + b*HH*64*SSP below
                if (r0 < M) {
                    int bi = (r0 >= SS) ? 1 : 0;
                    int s = r0 - bi * SS;
                    size_t o = (size_t)bi * HH * 64 * SSP + base + s;
                    C[o] = v00;
                    C[o + SSP] = v01;
                }
                if (r0 + 8 < M) {
                    int bi = (r0 + 8 >= SS) ? 1 : 0;
                    int s = r0 + 8 - bi * SS;
                    size_t o = (size_t)bi * HH * 64 * SSP + base + s;
                    C[o] = v10;
                    C[o + SSP] = v11;
                }
            }
        }
    }
#undef G_LDG
#undef G_STS
}

__global__ __launch_bounds__(256, 2) void qkv_gemm_kernel(
    const float* __restrict__ A,
    const float* __restrict__ Wq, const float* __restrict__ bq,
    const float* __restrict__ Wk, const float* __restrict__ bk,
    const float* __restrict__ Wv, const float* __restrict__ bv,
    float* __restrict__ Cq, float* __restrict__ Ck, float* __restrict__ Cv,
    int M)
{
    extern __shared__ float gsm[];
    if (blockIdx.z == 0)
        gemm_body<1>(A, Wq, bq, Cq, M, blockIdx.y * 128, blockIdx.x * 128, gsm);
    else if (blockIdx.z == 1)
        gemm_body<1>(A, Wk, bk, Ck, M, blockIdx.y * 128, blockIdx.x * 128, gsm);
    else
        gemm_body<2>(A, Wv, bv, Cv, M, blockIdx.y * 128, blockIdx.x * 128, gsm);
}

__global__ __launch_bounds__(256, 2) void gemm_tc_kernel(
    const float* __restrict__ A, const float* __restrict__ B,
    const float* __restrict__ bias, float* __restrict__ C, int M)
{
    extern __shared__ float gsm[];
    gemm_body<0>(A, B, bias, C, M, blockIdx.y * 128, blockIdx.x * 128, gsm);
}

// ---------------------------------------------------------------------------
// Gate dot products (g_q/g_k are column-permuted; index wg via inverse perm)
// ---------------------------------------------------------------------------
__global__ __launch_bounds__(128) void gate_kernel(const float* __restrict__ wg)
{
    const int row = blockIdx.x;
    const int tid = threadIdx.x;
    float sq = 0.f, sk = 0.f;
#pragma unroll
    for (int e = tid; e < 512; e += 128) {
        // stored position e holds original column o
        int o = (e & ~7) | (((e >> 1) & 3) + ((e & 1) << 2));
        sq += g_q[(size_t)row * 512 + e] * wg[o];
        sk += g_k[(size_t)row * 512 + e] * wg[512 + o];
    }
#pragma unroll
    for (int off = 16; off >= 1; off >>= 1) {
        sq += __shfl_down_sync(0xffffffffu, sq, off);
        sk += __shfl_down_sync(0xffffffffu, sk, off);
    }
    __shared__ float pq[4], pk[4];
    if ((tid & 31) == 0) { pq[tid >> 5] = sq; pk[tid >> 5] = sk; }
    __syncthreads();
    if (tid == 0) {
        g_gq[row] = pq[0] + pq[1] + pq[2] + pq[3];
        g_gk[row] = pk[0] + pk[1] + pk[2] + pk[3];
    }
}

// ---------------------------------------------------------------------------
// TF32 mma.sync flash attention, cp.async double-buffered K/V staging,
// register-resident P. GMEM-permuted Q/K and transposed V make every
// fragment load an LDS.64. R14: fixed egk pipeline (next-tile buffer
// written in-loop, matching the pre-advanced gk_reg; single sync/tile).
// ---------------------------------------------------------------------------
#define ASTR 72
#define TILE72 (64 * ASTR)
#define ATTN_SMEM ((5 * TILE72 + 128 + 16) * 4)

__global__ __launch_bounds__(128, 2) void attn_mma_kernel(const float* __restrict__ bg_ptr)
{
    extern __shared__ float sm[];
    float* Qs   = sm;                       // [64][ASTR]
    float* egk  = sm + 5 * TILE72;          // [2][64]

    const int qb = blockIdx.x, h = blockIdx.y, b = blockIdx.z;
    const int q0 = qb * 64;
    const int tid = threadIdx.x;
    const int lane = tid & 31;
    const int g = lane >> 2, tg = lane & 3;
    const int wrow = (tid >> 5) * 16;
    const float bg = bg_ptr[0];

    const float* qp = g_q + ((size_t)(b * SS)) * EE + h * 64;
    const float* kp = g_k + ((size_t)(b * SS)) * EE + h * 64;
    const float* vtp = g_vt + ((size_t)(b * HH + h)) * 64 * SSP;

    int kstart = q0 - WINW; if (kstart < 0) kstart = 0;
    int kend = q0 + 64 + WINW; if (kend > SS) kend = SS;

    const int s_r = tid >> 4, s_c = (tid & 15) * 4;
#define STAGE_KV(K0, BBUF)                                                     \
    {                                                                          \
        float* Kb = sm + (1 + (BBUF)) * TILE72;                                \
        float* Vb = sm + (3 + (BBUF)) * TILE72;                                \
        int remv = SS - (K0) - s_c;                                            \
        int zfv = (remv >= 4) ? 0 : ((remv > 0) ? (16 - 4 * remv) : 16);       \
        const float* vsrc = vtp + (K0) + ((remv > 0) ? s_c : 0);               \
        _Pragma("unroll")                                                      \
        for (int it = 0; it < 8; it++) {                                       \
            int r = s_r + it * 8;                                              \
            int gj = (K0) + r;                                                 \
            int zf = (gj < SS) ? 0 : 16;                                       \
            __pipeline_memcpy_async(&Kb[r * ASTR + s_c],                       \
                                    kp + (size_t)gj * EE + s_c, 16, zf);       \
            __pipeline_memcpy_async(&Vb[r * ASTR + s_c],                       \
                                    vsrc + (size_t)r * SSP, 16, zfv);          \
        }                                                                      \
        __pipeline_commit();                                                   \
    }

    STAGE_KV(kstart, 0);
    float gk_reg = 0.f;
    if (tid < 64) {
        int gj = kstart + tid;
        gk_reg = (gj < SS) ? g_gk[b * SS + gj] : 0.f;
    }

#pragma unroll
    for (int it = 0; it < 8; it++) {
        int idx = it * 128 + tid;
        int r = idx >> 4, c4 = (idx & 15) * 4;
        int gi = q0 + r;
        float4 v = make_float4(0.f, 0.f, 0.f, 0.f);
        if (gi < SS) v = *(const float4*)(qp + (size_t)gi * EE + c4);
        Qs[r * ASTR + c4 + 0] = tf32r(v.x);
        Qs[r * ASTR + c4 + 1] = tf32r(v.y);
        Qs[r * ASTR + c4 + 2] = tf32r(v.z);
        Qs[r * ASTR + c4 + 3] = tf32r(v.w);
    }
    // tile 0 egk -> buffer 0; pre-advance gk_reg to tile 1
    if (tid < 64) {
        egk[tid] = __expf(-gk_reg - bg);
        if (kstart + 64 < kend) {
            int gj = kstart + 64 + tid;
            gk_reg = (gj < SS) ? g_gk[b * SS + gj] : 0.f;
        }
    }
    __syncthreads();

    // Q A-fragments: permuted layout -> LDS.64 pairs
    uint32_t qa[8][4];
#pragma unroll
    for (int kk = 0; kk < 8; kk++) {
        float2 lo = *(const float2*)&Qs[(wrow + g) * ASTR + kk * 8 + 2 * tg];
        float2 hi = *(const float2*)&Qs[(wrow + g + 8) * ASTR + kk * 8 + 2 * tg];
        qa[kk][0] = __float_as_uint(lo.x);
        qa[kk][1] = __float_as_uint(hi.x);
        qa[kk][2] = __float_as_uint(lo.y);
        qa[kk][3] = __float_as_uint(hi.y);
    }
    const int gi0 = q0 + wrow + g, gi1 = gi0 + 8;
    const float egq0 = __expf(-((gi0 < SS) ? g_gq[b * SS + gi0] : 0.f));
    const float egq1 = __expf(-((gi1 < SS) ? g_gq[b * SS + gi1] : 0.f));

    float oacc[8][4];
#pragma unroll
    for (int nt = 0; nt < 8; nt++)
#pragma unroll
        for (int e = 0; e < 4; e++) oacc[nt][e] = 0.f;
    float l0 = 0.f, l1 = 0.f;

    const float C1 = SCALE * LOG2E;
    const float C2 = BIASC * LOG2E;

    int p = 0;
    for (int k0 = kstart; k0 < kend; k0 += 64, p ^= 1) {
        __pipeline_wait_prior(0);      // this tile's K/V landed
        __syncthreads();               // everyone done with buffer 1-p

        // stage NEXT tile (buffer 1-p) + its egk (gk_reg holds next tile's gk)
        if (k0 + 64 < kend) {
            STAGE_KV(k0 + 64, 1 - p);
            if (tid < 64) {
                egk[(1 - p) * 64 + tid] = __expf(-gk_reg - bg);
                if (k0 + 128 < kend) {
                    int gj = k0 + 128 + tid;
                    gk_reg = (gj < SS) ? g_gk[b * SS + gj] : 0.f;
                }
            }
        }

        const float* Kb = sm + (1 + p) * TILE72;
        const float* Vb = sm + (3 + p) * TILE72;
        const float* eg_s = egk + p * 64;

        // ---- S = Q @ K^T (K fragments: LDS.64) ----
        float sacc[8][4];
#pragma unroll
        for (int nt = 0; nt < 8; nt++)
#pragma unroll
            for (int e = 0; e < 4; e++) sacc[nt][e] = 0.f;
#pragma unroll
        for (int kk = 0; kk < 8; kk++) {
#pragma unroll
            for (int nt = 0; nt < 8; nt++) {
                float2 kv = *(const float2*)&Kb[(nt * 8 + g) * ASTR + kk * 8 + 2 * tg];
                uint32_t bf[2];
                bf[0] = __float_as_uint(kv.x);
                bf[1] = __float_as_uint(kv.y);
                mma_tf32(sacc[nt], qa[kk], bf);
            }
        }

        // ---- Epilogue: gate + bias + mask + exp; P stays in sacc regs ----
        float lt0 = 0.f, lt1 = 0.f;
#pragma unroll
        for (int nt = 0; nt < 8; nt++) {
            int lj = nt * 8 + 2 * tg;
            float2 eg = *(float2*)&eg_s[lj];
            int gj0 = k0 + lj, gj1 = gj0 + 1;

            int d00 = gi0 - gj0, d01 = gi0 - gj1, d10 = gi1 - gj0, d11 = gi1 - gj1;
            {
                float gate = rcpf(fmaf(egq0, eg.x, 1.f));
                float pe = ex2f((sacc[nt][0] * C1 + (float)(d00 * d00) * C2) * gate);
                sacc[nt][0] = (gj0 < SS && d00 <= WINW && d00 >= -WINW) ? tf32r(pe) : 0.f;
            }
            {
                float gate = rcpf(fmaf(egq0, eg.y, 1.f));
                float pe = ex2f((sacc[nt][1] * C1 + (float)(d01 * d01) * C2) * gate);
                sacc[nt][1] = (gj1 < SS && d01 <= WINW && d01 >= -WINW) ? tf32r(pe) : 0.f;
            }
            {
                float gate = rcpf(fmaf(egq1, eg.x, 1.f));
                float pe = ex2f((sacc[nt][2] * C1 + (float)(d10 * d10) * C2) * gate);
                sacc[nt][2] = (gj0 < SS && d10 <= WINW && d10 >= -WINW) ? tf32r(pe) : 0.f;
            }
            {
                float gate = rcpf(fmaf(egq1, eg.y, 1.f));
                float pe = ex2f((sacc[nt][3] * C1 + (float)(d11 * d11) * C2) * gate);
                sacc[nt][3] = (gj1 < SS && d11 <= WINW && d11 >= -WINW) ? tf32r(pe) : 0.f;
            }
            lt0 += sacc[nt][0] + sacc[nt][1];
            lt1 += sacc[nt][2] + sacc[nt][3];
        }
        lt0 += __shfl_xor_sync(0xffffffffu, lt0, 1);
        lt0 += __shfl_xor_sync(0xffffffffu, lt0, 2);
        lt1 += __shfl_xor_sync(0xffffffffu, lt1, 1);
        lt1 += __shfl_xor_sync(0xffffffffu, lt1, 2);
        l0 += lt0;
        l1 += lt1;

        // ---- O += P @ V (V transposed in smem: fragments are LDS.64) ----
#pragma unroll
        for (int kk = 0; kk < 8; kk++) {
            uint32_t pa[4];
            pa[0] = __float_as_uint(sacc[kk][0]);   // P[j=2tg]   -> k-slot tg
            pa[1] = __float_as_uint(sacc[kk][2]);
            pa[2] = __float_as_uint(sacc[kk][1]);   // P[j=2tg+1] -> k-slot tg+4
            pa[3] = __float_as_uint(sacc[kk][3]);
#pragma unroll
            for (int nt = 0; nt < 8; nt++) {
                float2 vv = *(const float2*)&Vb[(nt * 8 + g) * ASTR + kk * 8 + 2 * tg];
                uint32_t bf[2];
                bf[0] = __float_as_uint(vv.x);      // V[j=2tg]   -> k-slot tg
                bf[1] = __float_as_uint(vv.y);      // V[j=2tg+1] -> k-slot tg+4
                mma_tf32(oacc[nt], pa, bf);
            }
        }
    }

    const float inv0 = rcpf(l0), inv1 = rcpf(l1);
    float* op = g_ao + ((size_t)(b * SS)) * EE + h * 64;
#pragma unroll
    for (int nt = 0; nt < 8; nt++) {
        int c = nt * 8 + 2 * tg;
        if (gi0 < SS)
            *(float2*)&op[(size_t)gi0 * EE + c] =
                make_float2(oacc[nt][0] * inv0, oacc[nt][1] * inv0);
        if (gi1 < SS)
            *(float2*)&op[(size_t)gi1 * EE + c] =
                make_float2(oacc[nt][2] * inv1, oacc[nt][3] * inv1);
    }
#undef STAGE_KV
}

// ---------------------------------------------------------------------------
extern "C" void kernel_launch(void* const* d_in, const int* in_sizes, int n_in,
                              void* d_out, int out_size)
{
    const float* x  = (const float*)d_in[0];
    const float* Wq = (const float*)d_in[1];
    const float* bq = (const float*)d_in[2];
    const float* Wk = (const float*)d_in[3];
    const float* bk = (const float*)d_in[4];
    const float* Wv = (const float*)d_in[5];
    const float* bv = (const float*)d_in[6];
    const float* Wo = (const float*)d_in[7];
    const float* bo = (const float*)d_in[8];
    const float* wg = (const float*)d_in[9];
    const float* bg = (const float*)d_in[10];
    float* out = (float*)d_out;

    float *pq, *pk, *pvt, *pao;
    cudaGetSymbolAddress((void**)&pq, g_q);
    cudaGetSymbolAddress((void**)&pk, g_k);
    cudaGetSymbolAddress((void**)&pvt, g_vt);
    cudaGetSymbolAddress((void**)&pao, g_ao);

    cudaFuncSetAttribute(attn_mma_kernel,
                         cudaFuncAttributeMaxDynamicSharedMemorySize, ATTN_SMEM);
    cudaFuncSetAttribute(qkv_gemm_kernel,
                         cudaFuncAttributeMaxDynamicSharedMemorySize, GEMM_SMEM);
    cudaFuncSetAttribute(gemm_tc_kernel,
                         cudaFuncAttributeMaxDynamicSharedMemorySize, GEMM_SMEM);

    dim3 gqkv(4, 33, 3);
    qkv_gemm_kernel<<<gqkv, 256, GEMM_SMEM>>>(x, Wq, bq, Wk, bk, Wv, bv, pq, pk, pvt, MROWS);
    gate_kernel<<<MROWS, 128>>>(wg);
    attn_mma_kernel<<<dim3(33, HH, BB), 128, ATTN_SMEM>>>(bg);
    gemm_tc_kernel<<<dim3(4, 33), 256, GEMM_SMEM>>>(pao, Wo, bo, out, MROWS);
}

// round 15
// speedup vs baseline: 1.0169x; 1.0169x over previous
#include <cuda_runtime.h>
#include <cuda_pipeline.h>
#include <cstdint>
#include <math.h>

#define BB 2
#define SS 2049
#define SSP 2052
#define EE 512
#define HH 8
#define WINW 1024
#define MROWS (BB * SS)                  // 4098
#define SCALE 0.125f                     // D^-0.5
#define BIASC (-1.9073486328125e-6f)     // -0.5/(512^2)
#define LOG2E 1.4426950408889634f

// Scratch (device globals: no allocation allowed)
__device__ float g_q[MROWS * EE];        // column-permuted within 8-groups
__device__ float g_k[MROWS * EE];        // column-permuted within 8-groups
__device__ float g_vt[BB * HH * 64 * SSP]; // V transposed: [b][h][d][s]
__device__ float g_ao[MROWS * EE];
__device__ float g_gq[MROWS];
__device__ float g_gk[MROWS];

// ============================================================================
// helpers
// ============================================================================
__device__ __forceinline__ float tf32r(float x) {
    uint32_t u;
    asm("cvt.rna.tf32.f32 %0, %1;" : "=r"(u) : "f"(x));
    return __uint_as_float(u);
}
__device__ __forceinline__ void mma_tf32(float* d, const uint32_t* a, const uint32_t* b) {
    asm volatile(
        "mma.sync.aligned.m16n8k8.row.col.f32.tf32.tf32.f32 "
        "{%0,%1,%2,%3}, {%4,%5,%6,%7}, {%8,%9}, {%0,%1,%2,%3};"
        : "+f"(d[0]), "+f"(d[1]), "+f"(d[2]), "+f"(d[3])
        : "r"(a[0]), "r"(a[1]), "r"(a[2]), "r"(a[3]), "r"(b[0]), "r"(b[1]));
}
__device__ __forceinline__ float rcpf(float x) {
    float r;
    asm("rcp.approx.f32 %0, %1;" : "=f"(r) : "f"(x));
    return r;
}
__device__ __forceinline__ float ex2f(float x) {
    float r;
    asm("ex2.approx.f32 %0, %1;" : "=f"(r) : "f"(x));
    return r;
}
// within-8 permutation: original offset o -> stored position
__device__ __forceinline__ int perm8(int o) {
    return ((o & 3) << 1) | ((o >> 2) & 1);
}

// ---------------------------------------------------------------------------
// 1xTF32 GEMM body (rna-rounded at staging), software-pipelined
// double-buffered. BM=128 BN=128 BK=16, 256 thr, warp tile 32x64.
// MODE 0: normal row-major out; MODE 1: within-8 column-permuted out (Q,K);
// MODE 2: transposed out into g_vt (V).
// ---------------------------------------------------------------------------
#define GSTR 136
#define TILEF (16 * GSTR)
#define GEMM_SMEM (4 * TILEF * 4)

template <int MODE>
__device__ __forceinline__ void gemm_body(
    const float* __restrict__ A, const float* __restrict__ B,
    const float* __restrict__ bias, float* __restrict__ C, int M,
    int row0, int col0, float* sm)
{
    float* Ab = sm;
    float* Bb = sm + 2 * TILEF;

    const int tid = threadIdx.x;
    const int wid = tid >> 5, lane = tid & 31;
    const int g = lane >> 2, tg = lane & 3;
    const int wm = wid >> 1, wn = wid & 1;
    const int wrow = wm * 32, wcol = wn * 64;

    const int a_r0 = tid >> 2, a_c = (tid & 3) * 4;
    const int b_k0 = tid >> 5, b_c = (tid & 31) * 4;

    float acc[2][8][4];
#pragma unroll
    for (int mt = 0; mt < 2; mt++)
#pragma unroll
        for (int nt = 0; nt < 8; nt++)
#pragma unroll
            for (int e = 0; e < 4; e++) acc[mt][nt][e] = 0.f;

    float4 pa[2], pb[2];

#define G_LDG(K0)                                                              \
    {                                                                          \
        _Pragma("unroll")                                                      \
        for (int it = 0; it < 2; it++) {                                       \
            int r = a_r0 + it * 64;                                            \
            pa[it] = make_float4(0.f, 0.f, 0.f, 0.f);                          \
            if (row0 + r < M)                                                  \
                pa[it] = *(const float4*)&A[(size_t)(row0 + r) * 512 + (K0) + a_c]; \
            int kr = b_k0 + it * 8;                                            \
            pb[it] = *(const float4*)&B[(size_t)((K0) + kr) * 512 + col0 + b_c];    \
        }                                                                      \
    }

#define G_STS(Q)                                                               \
    {                                                                          \
        float* ab = Ab + (Q) * TILEF;                                          \
        float* bb = Bb + (Q) * TILEF;                                          \
        _Pragma("unroll")                                                      \
        for (int it = 0; it < 2; it++) {                                       \
            int r = a_r0 + it * 64;                                            \
            ab[(a_c + 0) * GSTR + r] = tf32r(pa[it].x);                        \
            ab[(a_c + 1) * GSTR + r] = tf32r(pa[it].y);                        \
            ab[(a_c + 2) * GSTR + r] = tf32r(pa[it].z);                        \
            ab[(a_c + 3) * GSTR + r] = tf32r(pa[it].w);                        \
            int kr = b_k0 + it * 8;                                            \
            float4 hv;                                                         \
            hv.x = tf32r(pb[it].x);                                            \
            hv.y = tf32r(pb[it].y);                                            \
            hv.z = tf32r(pb[it].z);                                            \
            hv.w = tf32r(pb[it].w);                                            \
            *(float4*)&bb[kr * GSTR + b_c] = hv;                               \
        }                                                                      \
    }

    G_LDG(0);
    G_STS(0);
    G_LDG(16);
    __syncthreads();

    int p = 0;
    for (int k0 = 0; k0 < 512; k0 += 16) {
        if (k0 + 16 < 512) {
            G_STS(1 - p);
            if (k0 + 32 < 512) G_LDG(k0 + 32);
        }

        const float* ab_ = Ab + p * TILEF;
        const float* bb_ = Bb + p * TILEF;
#pragma unroll
        for (int ks = 0; ks < 2; ks++) {
            const int kk = ks * 8;
            uint32_t af[2][4];
#pragma unroll
            for (int mt = 0; mt < 2; mt++) {
                int r = wrow + mt * 16;
                af[mt][0] = __float_as_uint(ab_[(kk + tg) * GSTR + r + g]);
                af[mt][1] = __float_as_uint(ab_[(kk + tg) * GSTR + r + g + 8]);
                af[mt][2] = __float_as_uint(ab_[(kk + tg + 4) * GSTR + r + g]);
                af[mt][3] = __float_as_uint(ab_[(kk + tg + 4) * GSTR + r + g + 8]);
            }
            uint32_t bf[8][2];
#pragma unroll
            for (int nt = 0; nt < 8; nt++) {
                int c = wcol + nt * 8;
                bf[nt][0] = __float_as_uint(bb_[(kk + tg) * GSTR + c + g]);
                bf[nt][1] = __float_as_uint(bb_[(kk + tg + 4) * GSTR + c + g]);
            }
#pragma unroll
            for (int mt = 0; mt < 2; mt++)
#pragma unroll
                for (int nt = 0; nt < 8; nt++)
                    mma_tf32(acc[mt][nt], af[mt], bf[nt]);
        }

        if (k0 + 16 < 512) {
            __syncthreads();
            p ^= 1;
        }
    }

#pragma unroll
    for (int mt = 0; mt < 2; mt++) {
        int r0 = row0 + wrow + mt * 16 + g;
#pragma unroll
        for (int nt = 0; nt < 8; nt++) {
            int c = col0 + wcol + nt * 8 + 2 * tg;
            float b0v = bias[c], b1v = bias[c + 1];
            float v00 = acc[mt][nt][0] + b0v, v01 = acc[mt][nt][1] + b1v;
            float v10 = acc[mt][nt][2] + b0v, v11 = acc[mt][nt][3] + b1v;
            if (MODE == 0) {
                if (r0 < M)
                    *(float2*)&C[(size_t)r0 * 512 + c] = make_float2(v00, v01);
                if (r0 + 8 < M)
                    *(float2*)&C[(size_t)(r0 + 8) * 512 + c] = make_float2(v10, v11);
            } else if (MODE == 1) {
                int c0p = (c & ~7) | perm8(c & 7);
                int c1p = (c & ~7) | perm8((c + 1) & 7);
                if (r0 < M) {
                    C[(size_t)r0 * 512 + c0p] = v00;
                    C[(size_t)r0 * 512 + c1p] = v01;
                }
                if (r0 + 8 < M) {
                    C[(size_t)(r0 + 8) * 512 + c0p] = v10;
                    C[(size_t)(r0 + 8) * 512 + c1p] = v11;
                }
            } else {
                int hh = c >> 6, d = c & 63;
                size_t base = ((size_t)hh * 64 + d) * SSP;   // + b*HH*64*SSP below
                if (r0 < M) {
                    int bi = (r0 >= SS) ? 1 : 0;
                    int s = r0 - bi * SS;
                    size_t o = (size_t)bi * HH * 64 * SSP + base + s;
                    C[o] = v00;
                    C[o + SSP] = v01;
                }
                if (r0 + 8 < M) {
                    int bi = (r0 + 8 >= SS) ? 1 : 0;
                    int s = r0 + 8 - bi * SS;
                    size_t o = (size_t)bi * HH * 64 * SSP + base + s;
                    C[o] = v10;
                    C[o + SSP] = v11;
                }
            }
        }
    }
#undef G_LDG
#undef G_STS
}

__global__ __launch_bounds__(256, 2) void qkv_gemm_kernel(
    const float* __restrict__ A,
    const float* __restrict__ Wq, const float* __restrict__ bq,
    const float* __restrict__ Wk, const float* __restrict__ bk,
    const float* __restrict__ Wv, const float* __restrict__ bv,
    float* __restrict__ Cq, float* __restrict__ Ck, float* __restrict__ Cv,
    int M)
{
    extern __shared__ float gsm[];
    if (blockIdx.z == 0)
        gemm_body<1>(A, Wq, bq, Cq, M, blockIdx.y * 128, blockIdx.x * 128, gsm);
    else if (blockIdx.z == 1)
        gemm_body<1>(A, Wk, bk, Ck, M, blockIdx.y * 128, blockIdx.x * 128, gsm);
    else
        gemm_body<2>(A, Wv, bv, Cv, M, blockIdx.y * 128, blockIdx.x * 128, gsm);
}

__global__ __launch_bounds__(256, 2) void gemm_tc_kernel(
    const float* __restrict__ A, const float* __restrict__ B,
    const float* __restrict__ bias, float* __restrict__ C, int M)
{
    extern __shared__ float gsm[];
    gemm_body<0>(A, B, bias, C, M, blockIdx.y * 128, blockIdx.x * 128, gsm);
}

// ---------------------------------------------------------------------------
// Gate dot products (g_q/g_k are column-permuted; index wg via inverse perm)
// ---------------------------------------------------------------------------
__global__ __launch_bounds__(128) void gate_kernel(const float* __restrict__ wg)
{
    const int row = blockIdx.x;
    const int tid = threadIdx.x;
    float sq = 0.f, sk = 0.f;
#pragma unroll
    for (int e = tid; e < 512; e += 128) {
        // stored position e holds original column o
        int o = (e & ~7) | (((e >> 1) & 3) + ((e & 1) << 2));
        sq += g_q[(size_t)row * 512 + e] * wg[o];
        sk += g_k[(size_t)row * 512 + e] * wg[512 + o];
    }
#pragma unroll
    for (int off = 16; off >= 1; off >>= 1) {
        sq += __shfl_down_sync(0xffffffffu, sq, off);
        sk += __shfl_down_sync(0xffffffffu, sk, off);
    }
    __shared__ float pq[4], pk[4];
    if ((tid & 31) == 0) { pq[tid >> 5] = sq; pk[tid >> 5] = sk; }
    __syncthreads();
    if (tid == 0) {
        g_gq[row] = pq[0] + pq[1] + pq[2] + pq[3];
        g_gk[row] = pk[0] + pk[1] + pk[2] + pk[3];
    }
}

// ---------------------------------------------------------------------------
// TF32 mma.sync flash attention. R15: Tq=128 (8 warps x 16 rows, 256 thr),
// Tk=64. K/V staged once per 128 q-rows (traffic halved), 4 warps/SMSP at
// occ 2, grid 272 -> single wave. Per-warp structure identical to R14.
// ---------------------------------------------------------------------------
#define ASTR 72
#define TILE72 (64 * ASTR)
#define QTILE (128 * ASTR)
// Qs(128) + Kb[2] + Vb[2] (64 each) + egk[2][64]
#define ATTN_SMEM ((QTILE + 4 * TILE72 + 128 + 16) * 4)

__global__ __launch_bounds__(256, 2) void attn_mma_kernel(const float* __restrict__ bg_ptr)
{
    extern __shared__ float sm[];
    float* Qs   = sm;                            // [128][ASTR]
    float* egk  = sm + QTILE + 4 * TILE72;       // [2][64]

    const int qb = blockIdx.x, h = blockIdx.y, b = blockIdx.z;
    const int q0 = qb * 128;
    const int tid = threadIdx.x;
    const int lane = tid & 31;
    const int g = lane >> 2, tg = lane & 3;
    const int wrow = (tid >> 5) * 16;            // 0..112
    const float bg = bg_ptr[0];

    const float* qp = g_q + ((size_t)(b * SS)) * EE + h * 64;
    const float* kp = g_k + ((size_t)(b * SS)) * EE + h * 64;
    const float* vtp = g_vt + ((size_t)(b * HH + h)) * 64 * SSP;

    int kstart = q0 - WINW; if (kstart < 0) kstart = 0;
    int kend = q0 + 128 + WINW; if (kend > SS) kend = SS;

    const int s_r = tid >> 4, s_c = (tid & 15) * 4;   // 16 rows per pass, 4 passes
#define STAGE_KV(K0, BBUF)                                                     \
    {                                                                          \
        float* Kb = sm + QTILE + (BBUF) * TILE72;                              \
        float* Vb = sm + QTILE + (2 + (BBUF)) * TILE72;                        \
        int remv = SS - (K0) - s_c;                                            \
        int zfv = (remv >= 4) ? 0 : ((remv > 0) ? (16 - 4 * remv) : 16);       \
        const float* vsrc = vtp + (K0) + ((remv > 0) ? s_c : 0);               \
        _Pragma("unroll")                                                      \
        for (int it = 0; it < 4; it++) {                                       \
            int r = s_r + it * 16;                                             \
            int gj = (K0) + r;                                                 \
            int zf = (gj < SS) ? 0 : 16;                                       \
            __pipeline_memcpy_async(&Kb[r * ASTR + s_c],                       \
                                    kp + (size_t)gj * EE + s_c, 16, zf);       \
            __pipeline_memcpy_async(&Vb[r * ASTR + s_c],                       \
                                    vsrc + (size_t)r * SSP, 16, zfv);          \
        }                                                                      \
        __pipeline_commit();                                                   \
    }

    STAGE_KV(kstart, 0);
    float gk_reg = 0.f;
    if (tid < 64) {
        int gj = kstart + tid;
        gk_reg = (gj < SS) ? g_gk[b * SS + gj] : 0.f;
    }

    // Stage Q: 128 rows x 16 float4 = 2048 transfers over 256 threads
#pragma unroll
    for (int it = 0; it < 8; it++) {
        int idx = it * 256 + tid;
        int r = idx >> 4, c4 = (idx & 15) * 4;
        int gi = q0 + r;
        float4 v = make_float4(0.f, 0.f, 0.f, 0.f);
        if (gi < SS) v = *(const float4*)(qp + (size_t)gi * EE + c4);
        Qs[r * ASTR + c4 + 0] = tf32r(v.x);
        Qs[r * ASTR + c4 + 1] = tf32r(v.y);
        Qs[r * ASTR + c4 + 2] = tf32r(v.z);
        Qs[r * ASTR + c4 + 3] = tf32r(v.w);
    }
    // tile 0 egk -> buffer 0; pre-advance gk_reg to tile 1
    if (tid < 64) {
        egk[tid] = __expf(-gk_reg - bg);
        if (kstart + 64 < kend) {
            int gj = kstart + 64 + tid;
            gk_reg = (gj < SS) ? g_gk[b * SS + gj] : 0.f;
        }
    }
    __syncthreads();

    // Q A-fragments (permuted layout -> LDS.64 pairs)
    uint32_t qa[8][4];
#pragma unroll
    for (int kk = 0; kk < 8; kk++) {
        float2 lo = *(const float2*)&Qs[(wrow + g) * ASTR + kk * 8 + 2 * tg];
        float2 hi = *(const float2*)&Qs[(wrow + g + 8) * ASTR + kk * 8 + 2 * tg];
        qa[kk][0] = __float_as_uint(lo.x);
        qa[kk][1] = __float_as_uint(hi.x);
        qa[kk][2] = __float_as_uint(lo.y);
        qa[kk][3] = __float_as_uint(hi.y);
    }
    const int gi0 = q0 + wrow + g, gi1 = gi0 + 8;
    const float egq0 = __expf(-((gi0 < SS) ? g_gq[b * SS + gi0] : 0.f));
    const float egq1 = __expf(-((gi1 < SS) ? g_gq[b * SS + gi1] : 0.f));

    float oacc[8][4];
#pragma unroll
    for (int nt = 0; nt < 8; nt++)
#pragma unroll
        for (int e = 0; e < 4; e++) oacc[nt][e] = 0.f;
    float l0 = 0.f, l1 = 0.f;

    const float C1 = SCALE * LOG2E;
    const float C2 = BIASC * LOG2E;

    int p = 0;
    for (int k0 = kstart; k0 < kend; k0 += 64, p ^= 1) {
        __pipeline_wait_prior(0);      // this tile's K/V landed
        __syncthreads();               // everyone done with buffer 1-p

        // stage NEXT tile (buffer 1-p) + its egk (gk_reg holds next tile's gk)
        if (k0 + 64 < kend) {
            STAGE_KV(k0 + 64, 1 - p);
            if (tid < 64) {
                egk[(1 - p) * 64 + tid] = __expf(-gk_reg - bg);
                if (k0 + 128 < kend) {
                    int gj = k0 + 128 + tid;
                    gk_reg = (gj < SS) ? g_gk[b * SS + gj] : 0.f;
                }
            }
        }

        const float* Kb = sm + QTILE + p * TILE72;
        const float* Vb = sm + QTILE + (2 + p) * TILE72;
        const float* eg_s = egk + p * 64;

        // ---- S = Q @ K^T (K fragments: LDS.64) ----
        float sacc[8][4];
#pragma unroll
        for (int nt = 0; nt < 8; nt++)
#pragma unroll
            for (int e = 0; e < 4; e++) sacc[nt][e] = 0.f;
#pragma unroll
        for (int kk = 0; kk < 8; kk++) {
#pragma unroll
            for (int nt = 0; nt < 8; nt++) {
                float2 kv = *(const float2*)&Kb[(nt * 8 + g) * ASTR + kk * 8 + 2 * tg];
                uint32_t bf[2];
                bf[0] = __float_as_uint(kv.x);
                bf[1] = __float_as_uint(kv.y);
                mma_tf32(sacc[nt], qa[kk], bf);
            }
        }

        // ---- Epilogue: gate + bias + mask + exp; P stays in sacc regs ----
        float lt0 = 0.f, lt1 = 0.f;
#pragma unroll
        for (int nt = 0; nt < 8; nt++) {
            int lj = nt * 8 + 2 * tg;
            float2 eg = *(float2*)&eg_s[lj];
            int gj0 = k0 + lj, gj1 = gj0 + 1;

            int d00 = gi0 - gj0, d01 = gi0 - gj1, d10 = gi1 - gj0, d11 = gi1 - gj1;
            {
                float gate = rcpf(fmaf(egq0, eg.x, 1.f));
                float pe = ex2f((sacc[nt][0] * C1 + (float)(d00 * d00) * C2) * gate);
                sacc[nt][0] = (gj0 < SS && d00 <= WINW && d00 >= -WINW) ? tf32r(pe) : 0.f;
            }
            {
                float gate = rcpf(fmaf(egq0, eg.y, 1.f));
                float pe = ex2f((sacc[nt][1] * C1 + (float)(d01 * d01) * C2) * gate);
                sacc[nt][1] = (gj1 < SS && d01 <= WINW && d01 >= -WINW) ? tf32r(pe) : 0.f;
            }
            {
                float gate = rcpf(fmaf(egq1, eg.x, 1.f));
                float pe = ex2f((sacc[nt][2] * C1 + (float)(d10 * d10) * C2) * gate);
                sacc[nt][2] = (gj0 < SS && d10 <= WINW && d10 >= -WINW) ? tf32r(pe) : 0.f;
            }
            {
                float gate = rcpf(fmaf(egq1, eg.y, 1.f));
                float pe = ex2f((sacc[nt][3] * C1 + (float)(d11 * d11) * C2) * gate);
                sacc[nt][3] = (gj1 < SS && d11 <= WINW && d11 >= -WINW) ? tf32r(pe) : 0.f;
            }
            lt0 += sacc[nt][0] + sacc[nt][1];
            lt1 += sacc[nt][2] + sacc[nt][3];
        }
        lt0 += __shfl_xor_sync(0xffffffffu, lt0, 1);
        lt0 += __shfl_xor_sync(0xffffffffu, lt0, 2);
        lt1 += __shfl_xor_sync(0xffffffffu, lt1, 1);
        lt1 += __shfl_xor_sync(0xffffffffu, lt1, 2);
        l0 += lt0;
        l1 += lt1;

        // ---- O += P @ V (V transposed in smem: fragments are LDS.64) ----
#pragma unroll
        for (int kk = 0; kk < 8; kk++) {
            uint32_t pa[4];
            pa[0] = __float_as_uint(sacc[kk][0]);   // P[j=2tg]   -> k-slot tg
            pa[1] = __float_as_uint(sacc[kk][2]);
            pa[2] = __float_as_uint(sacc[kk][1]);   // P[j=2tg+1] -> k-slot tg+4
            pa[3] = __float_as_uint(sacc[kk][3]);
#pragma unroll
            for (int nt = 0; nt < 8; nt++) {
                float2 vv = *(const float2*)&Vb[(nt * 8 + g) * ASTR + kk * 8 + 2 * tg];
                uint32_t bf[2];
                bf[0] = __float_as_uint(vv.x);      // V[j=2tg]   -> k-slot tg
                bf[1] = __float_as_uint(vv.y);      // V[j=2tg+1] -> k-slot tg+4
                mma_tf32(oacc[nt], pa, bf);
            }
        }
    }

    const float inv0 = rcpf(l0), inv1 = rcpf(l1);
    float* op = g_ao + ((size_t)(b * SS)) * EE + h * 64;
#pragma unroll
    for (int nt = 0; nt < 8; nt++) {
        int c = nt * 8 + 2 * tg;
        if (gi0 < SS)
            *(float2*)&op[(size_t)gi0 * EE + c] =
                make_float2(oacc[nt][0] * inv0, oacc[nt][1] * inv0);
        if (gi1 < SS)
            *(float2*)&op[(size_t)gi1 * EE + c] =
                make_float2(oacc[nt][2] * inv1, oacc[nt][3] * inv1);
    }
#undef STAGE_KV
}

// ---------------------------------------------------------------------------
extern "C" void kernel_launch(void* const* d_in, const int* in_sizes, int n_in,
                              void* d_out, int out_size)
{
    const float* x  = (const float*)d_in[0];
    const float* Wq = (const float*)d_in[1];
    const float* bq = (const float*)d_in[2];
    const float* Wk = (const float*)d_in[3];
    const float* bk = (const float*)d_in[4];
    const float* Wv = (const float*)d_in[5];
    const float* bv = (const float*)d_in[6];
    const float* Wo = (const float*)d_in[7];
    const float* bo = (const float*)d_in[8];
    const float* wg = (const float*)d_in[9];
    const float* bg = (const float*)d_in[10];
    float* out = (float*)d_out;

    float *pq, *pk, *pvt, *pao;
    cudaGetSymbolAddress((void**)&pq, g_q);
    cudaGetSymbolAddress((void**)&pk, g_k);
    cudaGetSymbolAddress((void**)&pvt, g_vt);
    cudaGetSymbolAddress((void**)&pao, g_ao);

    cudaFuncSetAttribute(attn_mma_kernel,
                         cudaFuncAttributeMaxDynamicSharedMemorySize, ATTN_SMEM);
    cudaFuncSetAttribute(qkv_gemm_kernel,
                         cudaFuncAttributeMaxDynamicSharedMemorySize, GEMM_SMEM);
    cudaFuncSetAttribute(gemm_tc_kernel,
                         cudaFuncAttributeMaxDynamicSharedMemorySize, GEMM_SMEM);

    dim3 gqkv(4, 33, 3);
    qkv_gemm_kernel<<<gqkv, 256, GEMM_SMEM>>>(x, Wq, bq, Wk, bk, Wv, bv, pq, pk, pvt, MROWS);
    gate_kernel<<<MROWS, 128>>>(wg);
    attn_mma_kernel<<<dim3(17, HH, BB), 256, ATTN_SMEM>>>(bg);
    gemm_tc_kernel<<<dim3(4, 33), 256, GEMM_SMEM>>>(pao, Wo, bo, out, MROWS);
}

// round 16
// speedup vs baseline: 1.2550x; 1.2341x over previous
#include <cuda_runtime.h>
#include <cuda_pipeline.h>
#include <cuda_fp16.h>
#include <cstdint>
#include <math.h>

#define BB 2
#define SS 2049
#define SSPH 2056                        // padded S for g_vt16 (16B-aligned rows)
#define EE 512
#define HH 8
#define WINW 1024
#define MROWS (BB * SS)                  // 4098
#define SCALE 0.125f                     // D^-0.5
#define BIASC (-1.9073486328125e-6f)     // -0.5/(512^2)
#define LOG2E 1.4426950408889634f

// Scratch (device globals: no allocation allowed)
__device__ __half g_q16[MROWS * EE];          // Q projections, fp16
__device__ __half g_k16[MROWS * EE];          // K projections, fp16
__device__ __half g_vt16[BB * HH * 64 * SSPH]; // V transposed [b][h][d][s], fp16
__device__ float  g_ao[MROWS * EE];
__device__ float  g_gq[MROWS];
__device__ float  g_gk[MROWS];

// ============================================================================
// helpers
// ============================================================================
__device__ __forceinline__ float tf32r(float x) {
    uint32_t u;
    asm("cvt.rna.tf32.f32 %0, %1;" : "=r"(u) : "f"(x));
    return __uint_as_float(u);
}
__device__ __forceinline__ void mma_tf32(float* d, const uint32_t* a, const uint32_t* b) {
    asm volatile(
        "mma.sync.aligned.m16n8k8.row.col.f32.tf32.tf32.f32 "
        "{%0,%1,%2,%3}, {%4,%5,%6,%7}, {%8,%9}, {%0,%1,%2,%3};"
        : "+f"(d[0]), "+f"(d[1]), "+f"(d[2]), "+f"(d[3])
        : "r"(a[0]), "r"(a[1]), "r"(a[2]), "r"(a[3]), "r"(b[0]), "r"(b[1]));
}
__device__ __forceinline__ void mma_f16(float* d, const uint32_t* a, const uint32_t* b) {
    asm volatile(
        "mma.sync.aligned.m16n8k16.row.col.f32.f16.f16.f32 "
        "{%0,%1,%2,%3}, {%4,%5,%6,%7}, {%8,%9}, {%0,%1,%2,%3};"
        : "+f"(d[0]), "+f"(d[1]), "+f"(d[2]), "+f"(d[3])
        : "r"(a[0]), "r"(a[1]), "r"(a[2]), "r"(a[3]), "r"(b[0]), "r"(b[1]));
}
__device__ __forceinline__ uint32_t pack_h2(float lo, float hi) {
    __half2 h = __floats2half2_rn(lo, hi);   // lo -> low 16 bits
    return *(uint32_t*)&h;
}
__device__ __forceinline__ float rcpf(float x) {
    float r;
    asm("rcp.approx.f32 %0, %1;" : "=f"(r) : "f"(x));
    return r;
}
__device__ __forceinline__ float ex2f(float x) {
    float r;
    asm("ex2.approx.f32 %0, %1;" : "=f"(r) : "f"(x));
    return r;
}

// ---------------------------------------------------------------------------
// 1xTF32 GEMM body (rna-rounded at staging), software-pipelined
// double-buffered. BM=128 BN=128 BK=16, 256 thr, warp tile 32x64.
// MODE 0: fp32 row-major out; MODE 1: fp16 row-major out (Q,K);
// MODE 2: fp16 transposed out into g_vt16 (V).
// ---------------------------------------------------------------------------
#define GSTR 136
#define TILEF (16 * GSTR)
#define GEMM_SMEM (4 * TILEF * 4)

template <int MODE>
__device__ __forceinline__ void gemm_body(
    const float* __restrict__ A, const float* __restrict__ B,
    const float* __restrict__ bias, void* __restrict__ Cout, int M,
    int row0, int col0, float* sm)
{
    float* Ab = sm;
    float* Bb = sm + 2 * TILEF;

    const int tid = threadIdx.x;
    const int wid = tid >> 5, lane = tid & 31;
    const int g = lane >> 2, tg = lane & 3;
    const int wm = wid >> 1, wn = wid & 1;
    const int wrow = wm * 32, wcol = wn * 64;

    const int a_r0 = tid >> 2, a_c = (tid & 3) * 4;
    const int b_k0 = tid >> 5, b_c = (tid & 31) * 4;

    float acc[2][8][4];
#pragma unroll
    for (int mt = 0; mt < 2; mt++)
#pragma unroll
        for (int nt = 0; nt < 8; nt++)
#pragma unroll
            for (int e = 0; e < 4; e++) acc[mt][nt][e] = 0.f;

    float4 pa[2], pb[2];

#define G_LDG(K0)                                                              \
    {                                                                          \
        _Pragma("unroll")                                                      \
        for (int it = 0; it < 2; it++) {                                       \
            int r = a_r0 + it * 64;                                            \
            pa[it] = make_float4(0.f, 0.f, 0.f, 0.f);                          \
            if (row0 + r < M)                                                  \
                pa[it] = *(const float4*)&A[(size_t)(row0 + r) * 512 + (K0) + a_c]; \
            int kr = b_k0 + it * 8;                                            \
            pb[it] = *(const float4*)&B[(size_t)((K0) + kr) * 512 + col0 + b_c];    \
        }                                                                      \
    }

#define G_STS(Q)                                                               \
    {                                                                          \
        float* ab = Ab + (Q) * TILEF;                                          \
        float* bb = Bb + (Q) * TILEF;                                          \
        _Pragma("unroll")                                                      \
        for (int it = 0; it < 2; it++) {                                       \
            int r = a_r0 + it * 64;                                            \
            ab[(a_c + 0) * GSTR + r] = tf32r(pa[it].x);                        \
            ab[(a_c + 1) * GSTR + r] = tf32r(pa[it].y);                        \
            ab[(a_c + 2) * GSTR + r] = tf32r(pa[it].z);                        \
            ab[(a_c + 3) * GSTR + r] = tf32r(pa[it].w);                        \
            int kr = b_k0 + it * 8;                                            \
            float4 hv;                                                         \
            hv.x = tf32r(pb[it].x);                                            \
            hv.y = tf32r(pb[it].y);                                            \
            hv.z = tf32r(pb[it].z);                                            \
            hv.w = tf32r(pb[it].w);                                            \
            *(float4*)&bb[kr * GSTR + b_c] = hv;                               \
        }                                                                      \
    }

    G_LDG(0);
    G_STS(0);
    G_LDG(16);
    __syncthreads();

    int p = 0;
    for (int k0 = 0; k0 < 512; k0 += 16) {
        if (k0 + 16 < 512) {
            G_STS(1 - p);
            if (k0 + 32 < 512) G_LDG(k0 + 32);
        }

        const float* ab_ = Ab + p * TILEF;
        const float* bb_ = Bb + p * TILEF;
#pragma unroll
        for (int ks = 0; ks < 2; ks++) {
            const int kk = ks * 8;
            uint32_t af[2][4];
#pragma unroll
            for (int mt = 0; mt < 2; mt++) {
                int r = wrow + mt * 16;
                af[mt][0] = __float_as_uint(ab_[(kk + tg) * GSTR + r + g]);
                af[mt][1] = __float_as_uint(ab_[(kk + tg) * GSTR + r + g + 8]);
                af[mt][2] = __float_as_uint(ab_[(kk + tg + 4) * GSTR + r + g]);
                af[mt][3] = __float_as_uint(ab_[(kk + tg + 4) * GSTR + r + g + 8]);
            }
            uint32_t bf[8][2];
#pragma unroll
            for (int nt = 0; nt < 8; nt++) {
                int c = wcol + nt * 8;
                bf[nt][0] = __float_as_uint(bb_[(kk + tg) * GSTR + c + g]);
                bf[nt][1] = __float_as_uint(bb_[(kk + tg + 4) * GSTR + c + g]);
            }
#pragma unroll
            for (int mt = 0; mt < 2; mt++)
#pragma unroll
                for (int nt = 0; nt < 8; nt++)
                    mma_tf32(acc[mt][nt], af[mt], bf[nt]);
        }

        if (k0 + 16 < 512) {
            __syncthreads();
            p ^= 1;
        }
    }

#pragma unroll
    for (int mt = 0; mt < 2; mt++) {
        int r0 = row0 + wrow + mt * 16 + g;
#pragma unroll
        for (int nt = 0; nt < 8; nt++) {
            int c = col0 + wcol + nt * 8 + 2 * tg;
            float b0v = bias[c], b1v = bias[c + 1];
            float v00 = acc[mt][nt][0] + b0v, v01 = acc[mt][nt][1] + b1v;
            float v10 = acc[mt][nt][2] + b0v, v11 = acc[mt][nt][3] + b1v;
            if (MODE == 0) {
                float* C = (float*)Cout;
                if (r0 < M)
                    *(float2*)&C[(size_t)r0 * 512 + c] = make_float2(v00, v01);
                if (r0 + 8 < M)
                    *(float2*)&C[(size_t)(r0 + 8) * 512 + c] = make_float2(v10, v11);
            } else if (MODE == 1) {
                __half* C16 = (__half*)Cout;
                if (r0 < M)
                    *(__half2*)&C16[(size_t)r0 * 512 + c] = __floats2half2_rn(v00, v01);
                if (r0 + 8 < M)
                    *(__half2*)&C16[(size_t)(r0 + 8) * 512 + c] = __floats2half2_rn(v10, v11);
            } else {
                __half* C16 = (__half*)Cout;
                int hh = c >> 6, d = c & 63;
                size_t base = ((size_t)hh * 64 + d) * SSPH;
                if (r0 < M) {
                    int bi = (r0 >= SS) ? 1 : 0;
                    int s = r0 - bi * SS;
                    size_t o = (size_t)bi * HH * 64 * SSPH + base + s;
                    C16[o] = __float2half_rn(v00);
                    C16[o + SSPH] = __float2half_rn(v01);
                }
                if (r0 + 8 < M) {
                    int bi = (r0 + 8 >= SS) ? 1 : 0;
                    int s = r0 + 8 - bi * SS;
                    size_t o = (size_t)bi * HH * 64 * SSPH + base + s;
                    C16[o] = __float2half_rn(v10);
                    C16[o + SSPH] = __float2half_rn(v11);
                }
            }
        }
    }
#undef G_LDG
#undef G_STS
}

__global__ __launch_bounds__(256, 2) void qkv_gemm_kernel(
    const float* __restrict__ A,
    const float* __restrict__ Wq, const float* __restrict__ bq,
    const float* __restrict__ Wk, const float* __restrict__ bk,
    const float* __restrict__ Wv, const float* __restrict__ bv,
    void* Cq, void* Ck, void* Cv, int M)
{
    extern __shared__ float gsm[];
    if (blockIdx.z == 0)
        gemm_body<1>(A, Wq, bq, Cq, M, blockIdx.y * 128, blockIdx.x * 128, gsm);
    else if (blockIdx.z == 1)
        gemm_body<1>(A, Wk, bk, Ck, M, blockIdx.y * 128, blockIdx.x * 128, gsm);
    else
        gemm_body<2>(A, Wv, bv, Cv, M, blockIdx.y * 128, blockIdx.x * 128, gsm);
}

__global__ __launch_bounds__(256, 2) void gemm_tc_kernel(
    const float* __restrict__ A, const float* __restrict__ B,
    const float* __restrict__ bias, float* __restrict__ C, int M)
{
    extern __shared__ float gsm[];
    gemm_body<0>(A, B, bias, C, M, blockIdx.y * 128, blockIdx.x * 128, gsm);
}

// ---------------------------------------------------------------------------
// Gate dot products (reads fp16 q/k)
// ---------------------------------------------------------------------------
__global__ __launch_bounds__(128) void gate_kernel(const float* __restrict__ wg)
{
    const int row = blockIdx.x;
    const int tid = threadIdx.x;
    float sq = 0.f, sk = 0.f;
#pragma unroll
    for (int e = tid; e < 512; e += 128) {
        sq += __half2float(g_q16[(size_t)row * 512 + e]) * wg[e];
        sk += __half2float(g_k16[(size_t)row * 512 + e]) * wg[512 + e];
    }
#pragma unroll
    for (int off = 16; off >= 1; off >>= 1) {
        sq += __shfl_down_sync(0xffffffffu, sq, off);
        sk += __shfl_down_sync(0xffffffffu, sk, off);
    }
    __shared__ float pq[4], pk[4];
    if ((tid & 31) == 0) { pq[tid >> 5] = sq; pk[tid >> 5] = sk; }
    __syncthreads();
    if (tid == 0) {
        g_gq[row] = pq[0] + pq[1] + pq[2] + pq[3];
        g_gk[row] = pk[0] + pk[1] + pk[2] + pk[3];
    }
}

// ---------------------------------------------------------------------------
// FP16 mma.sync flash attention (m16n8k16, fp32 accum).
// Tq=128 (8 warps x 16 rows, 256 thr), Tk=64, occ 2, grid 272 (one wave).
// K smem [j][d], Vt smem [d][j], both fp16 stride 72 halves (conflict-free).
// Crossbar bytes and mma count both halved vs tf32 path.
// ---------------------------------------------------------------------------
#define HSTR 72
#define QBYTES (128 * HSTR * 2)          // 18432
#define TBYTES (64 * HSTR * 2)           // 9216
#define ATTN_SMEM (QBYTES + 4 * TBYTES + 512 + 64)

__global__ __launch_bounds__(256, 2) void attn_mma_kernel(const float* __restrict__ bg_ptr)
{
    extern __shared__ char smc[];
    __half* Qs   = (__half*)smc;                         // [128][HSTR]
    __half* Kbuf = (__half*)(smc + QBYTES);              // [2][64*HSTR]
    __half* Vbuf = (__half*)(smc + QBYTES + 2 * TBYTES); // [2][64*HSTR]
    float*  egk  = (float*)(smc + QBYTES + 4 * TBYTES);  // [2][64]

    const int qb = blockIdx.x, h = blockIdx.y, b = blockIdx.z;
    const int q0 = qb * 128;
    const int tid = threadIdx.x;
    const int lane = tid & 31;
    const int g = lane >> 2, tg = lane & 3;
    const int wrow = (tid >> 5) * 16;
    const float bg = bg_ptr[0];

    const __half* qp16 = g_q16 + (size_t)(b * SS) * 512 + h * 64;
    const __half* kp16 = g_k16 + (size_t)(b * SS) * 512 + h * 64;
    const __half* vtp16 = g_vt16 + ((size_t)(b * HH + h)) * 64 * SSPH;

    int kstart = q0 - WINW; if (kstart < 0) kstart = 0;
    int kend = q0 + 128 + WINW; if (kend > SS) kend = SS;

#define STAGE_KV(K0, BBUF)                                                     \
    {                                                                          \
        __half* Kb = Kbuf + (BBUF) * (64 * HSTR);                              \
        __half* Vb = Vbuf + (BBUF) * (64 * HSTR);                              \
        int kr = tid >> 2;                                                     \
        int coff = (tid & 3) * 16;                                             \
        int gj = (K0) + kr;                                                    \
        int zfk = (gj < SS) ? 0 : 16;                                          \
        const __half* ksrc = kp16 + (size_t)gj * 512;                          \
        _Pragma("unroll")                                                      \
        for (int it = 0; it < 2; it++) {                                       \
            int c8 = coff + it * 8;                                            \
            __pipeline_memcpy_async(&Kb[kr * HSTR + c8], ksrc + c8, 16, zfk);  \
            int remv = SS - (K0) - c8;                                         \
            int zfv = (remv >= 8) ? 0 : ((remv > 0) ? (16 - 2 * remv) : 16);   \
            __pipeline_memcpy_async(&Vb[kr * HSTR + c8],                       \
                                    vtp16 + (size_t)kr * SSPH + (K0) + c8,     \
                                    16, zfv);                                  \
        }                                                                      \
        __pipeline_commit();                                                   \
    }

    // prologue: tile-0 K/V + Q via cp.async
    STAGE_KV(kstart, 0);
    float gk_reg = 0.f;
    if (tid < 64) {
        int gj = kstart + tid;
        gk_reg = (gj < SS) ? g_gk[b * SS + gj] : 0.f;
    }
#pragma unroll
    for (int it = 0; it < 4; it++) {
        int idx = it * 256 + tid;            // 0..1023
        int r = idx >> 3, c8 = (idx & 7) * 8;
        int gi = q0 + r;
        int zf = (gi < SS) ? 0 : 16;
        __pipeline_memcpy_async(&Qs[r * HSTR + c8],
                                qp16 + (size_t)gi * 512 + c8, 16, zf);
    }
    __pipeline_commit();

    // tile 0 egk -> buffer 0; pre-advance gk_reg to tile 1
    if (tid < 64) {
        egk[tid] = __expf(-gk_reg - bg);
        if (kstart + 64 < kend) {
            int gj = kstart + 64 + tid;
            gk_reg = (gj < SS) ? g_gk[b * SS + gj] : 0.f;
        }
    }
    __pipeline_wait_prior(0);
    __syncthreads();

    // Q A-fragments (m16n8k16): qa[kc] = rows {g, g+8} x k {2tg,2tg+1, +8}
    uint32_t qa[4][4];
#pragma unroll
    for (int kc = 0; kc < 4; kc++) {
        qa[kc][0] = *(const uint32_t*)&Qs[(wrow + g) * HSTR + kc * 16 + 2 * tg];
        qa[kc][1] = *(const uint32_t*)&Qs[(wrow + g + 8) * HSTR + kc * 16 + 2 * tg];
        qa[kc][2] = *(const uint32_t*)&Qs[(wrow + g) * HSTR + kc * 16 + 2 * tg + 8];
        qa[kc][3] = *(const uint32_t*)&Qs[(wrow + g + 8) * HSTR + kc * 16 + 2 * tg + 8];
    }
    const int gi0 = q0 + wrow + g, gi1 = gi0 + 8;
    const float egq0 = __expf(-((gi0 < SS) ? g_gq[b * SS + gi0] : 0.f));
    const float egq1 = __expf(-((gi1 < SS) ? g_gq[b * SS + gi1] : 0.f));

    float oacc[8][4];
#pragma unroll
    for (int nt = 0; nt < 8; nt++)
#pragma unroll
        for (int e = 0; e < 4; e++) oacc[nt][e] = 0.f;
    float l0 = 0.f, l1 = 0.f;

    const float C1 = SCALE * LOG2E;
    const float C2 = BIASC * LOG2E;

    int p = 0;
    for (int k0 = kstart; k0 < kend; k0 += 64, p ^= 1) {
        __pipeline_wait_prior(0);      // this tile's K/V landed
        __syncthreads();               // everyone done with buffer 1-p

        if (k0 + 64 < kend) {
            STAGE_KV(k0 + 64, 1 - p);
            if (tid < 64) {
                egk[(1 - p) * 64 + tid] = __expf(-gk_reg - bg);
                if (k0 + 128 < kend) {
                    int gj = k0 + 128 + tid;
                    gk_reg = (gj < SS) ? g_gk[b * SS + gj] : 0.f;
                }
            }
        }

        const __half* Kb = Kbuf + p * (64 * HSTR);
        const __half* Vb = Vbuf + p * (64 * HSTR);
        const float* eg_s = egk + p * 64;

        // ---- S = Q @ K^T (fp16 m16n8k16: 32 mma) ----
        float sacc[8][4];
#pragma unroll
        for (int nt = 0; nt < 8; nt++)
#pragma unroll
            for (int e = 0; e < 4; e++) sacc[nt][e] = 0.f;
#pragma unroll
        for (int kc = 0; kc < 4; kc++) {
#pragma unroll
            for (int nt = 0; nt < 8; nt++) {
                uint32_t bf[2];
                bf[0] = *(const uint32_t*)&Kb[(nt * 8 + g) * HSTR + kc * 16 + 2 * tg];
                bf[1] = *(const uint32_t*)&Kb[(nt * 8 + g) * HSTR + kc * 16 + 2 * tg + 8];
                mma_f16(sacc[nt], qa[kc], bf);
            }
        }

        // ---- Epilogue: gate + bias + mask + exp; P stays in sacc regs ----
        float lt0 = 0.f, lt1 = 0.f;
#pragma unroll
        for (int nt = 0; nt < 8; nt++) {
            int lj = nt * 8 + 2 * tg;
            float2 eg = *(float2*)&eg_s[lj];
            int gj0 = k0 + lj, gj1 = gj0 + 1;

            int d00 = gi0 - gj0, d01 = gi0 - gj1, d10 = gi1 - gj0, d11 = gi1 - gj1;
            {
                float gate = rcpf(fmaf(egq0, eg.x, 1.f));
                float pe = ex2f((sacc[nt][0] * C1 + (float)(d00 * d00) * C2) * gate);
                sacc[nt][0] = (gj0 < SS && d00 <= WINW && d00 >= -WINW) ? pe : 0.f;
            }
            {
                float gate = rcpf(fmaf(egq0, eg.y, 1.f));
                float pe = ex2f((sacc[nt][1] * C1 + (float)(d01 * d01) * C2) * gate);
                sacc[nt][1] = (gj1 < SS && d01 <= WINW && d01 >= -WINW) ? pe : 0.f;
            }
            {
                float gate = rcpf(fmaf(egq1, eg.x, 1.f));
                float pe = ex2f((sacc[nt][2] * C1 + (float)(d10 * d10) * C2) * gate);
                sacc[nt][2] = (gj0 < SS && d10 <= WINW && d10 >= -WINW) ? pe : 0.f;
            }
            {
                float gate = rcpf(fmaf(egq1, eg.y, 1.f));
                float pe = ex2f((sacc[nt][3] * C1 + (float)(d11 * d11) * C2) * gate);
                sacc[nt][3] = (gj1 < SS && d11 <= WINW && d11 >= -WINW) ? pe : 0.f;
            }
            lt0 += sacc[nt][0] + sacc[nt][1];
            lt1 += sacc[nt][2] + sacc[nt][3];
        }
        lt0 += __shfl_xor_sync(0xffffffffu, lt0, 1);
        lt0 += __shfl_xor_sync(0xffffffffu, lt0, 2);
        lt1 += __shfl_xor_sync(0xffffffffu, lt1, 1);
        lt1 += __shfl_xor_sync(0xffffffffu, lt1, 2);
        l0 += lt0;
        l1 += lt1;

        // ---- O += P @ V (P packed to fp16 in regs; V fragments LDS.32) ----
#pragma unroll
        for (int kc = 0; kc < 4; kc++) {
            uint32_t pa[4];
            pa[0] = pack_h2(sacc[2 * kc][0],     sacc[2 * kc][1]);
            pa[1] = pack_h2(sacc[2 * kc][2],     sacc[2 * kc][3]);
            pa[2] = pack_h2(sacc[2 * kc + 1][0], sacc[2 * kc + 1][1]);
            pa[3] = pack_h2(sacc[2 * kc + 1][2], sacc[2 * kc + 1][3]);
#pragma unroll
            for (int nt = 0; nt < 8; nt++) {
                uint32_t bf[2];
                bf[0] = *(const uint32_t*)&Vb[(nt * 8 + g) * HSTR + kc * 16 + 2 * tg];
                bf[1] = *(const uint32_t*)&Vb[(nt * 8 + g) * HSTR + kc * 16 + 2 * tg + 8];
                mma_f16(oacc[nt], pa, bf);
            }
        }
    }

    const float inv0 = rcpf(l0), inv1 = rcpf(l1);
    float* op = g_ao + ((size_t)(b * SS)) * EE + h * 64;
#pragma unroll
    for (int nt = 0; nt < 8; nt++) {
        int c = nt * 8 + 2 * tg;
        if (gi0 < SS)
            *(float2*)&op[(size_t)gi0 * EE + c] =
                make_float2(oacc[nt][0] * inv0, oacc[nt][1] * inv0);
        if (gi1 < SS)
            *(float2*)&op[(size_t)gi1 * EE + c] =
                make_float2(oacc[nt][2] * inv1, oacc[nt][3] * inv1);
    }
#undef STAGE_KV
}

// ---------------------------------------------------------------------------
extern "C" void kernel_launch(void* const* d_in, const int* in_sizes, int n_in,
                              void* d_out, int out_size)
{
    const float* x  = (const float*)d_in[0];
    const float* Wq = (const float*)d_in[1];
    const float* bq = (const float*)d_in[2];
    const float* Wk = (const float*)d_in[3];
    const float* bk = (const float*)d_in[4];
    const float* Wv = (const float*)d_in[5];
    const float* bv = (const float*)d_in[6];
    const float* Wo = (const float*)d_in[7];
    const float* bo = (const float*)d_in[8];
    const float* wg = (const float*)d_in[9];
    const float* bg = (const float*)d_in[10];
    float* out = (float*)d_out;

    void *pq16, *pk16, *pvt16;
    float* pao;
    cudaGetSymbolAddress(&pq16, g_q16);
    cudaGetSymbolAddress(&pk16, g_k16);
    cudaGetSymbolAddress(&pvt16, g_vt16);
    cudaGetSymbolAddress((void**)&pao, g_ao);

    cudaFuncSetAttribute(attn_mma_kernel,
                         cudaFuncAttributeMaxDynamicSharedMemorySize, ATTN_SMEM);
    cudaFuncSetAttribute(qkv_gemm_kernel,
                         cudaFuncAttributeMaxDynamicSharedMemorySize, GEMM_SMEM);
    cudaFuncSetAttribute(gemm_tc_kernel,
                         cudaFuncAttributeMaxDynamicSharedMemorySize, GEMM_SMEM);

    dim3 gqkv(4, 33, 3);
    qkv_gemm_kernel<<<gqkv, 256, GEMM_SMEM>>>(x, Wq, bq, Wk, bk, Wv, bv,
                                              pq16, pk16, pvt16, MROWS);
    gate_kernel<<<MROWS, 128>>>(wg);
    attn_mma_kernel<<<dim3(17, HH, BB), 256, ATTN_SMEM>>>(bg);
    gemm_tc_kernel<<<dim3(4, 33), 256, GEMM_SMEM>>>(pao, Wo, bo, out, MROWS);
}

// round 17
// speedup vs baseline: 1.4395x; 1.1471x over previous
#include <cuda_runtime.h>
#include <cuda_pipeline.h>
#include <cuda_fp16.h>
#include <cstdint>
#include <math.h>

#define BB 2
#define SS 2049
#define SSPH 2056                        // padded S for g_vt16 (16B-aligned rows)
#define EE 512
#define HH 8
#define WINW 1024
#define MROWS (BB * SS)                  // 4098
#define SCALE 0.125f                     // D^-0.5
#define BIASC (-1.9073486328125e-6f)     // -0.5/(512^2)
#define LOG2E 1.4426950408889634f

// Scratch (device globals: no allocation allowed)
__device__ __half g_q16[MROWS * EE];          // Q projections, fp16
__device__ __half g_k16[MROWS * EE];          // K projections, fp16
__device__ __half g_vt16[BB * HH * 64 * SSPH]; // V transposed [b][h][d][s], fp16
__device__ __half g_wt[4 * EE * EE];          // W^T [n][k] fp16: Wq,Wk,Wv,Wo
__device__ float  g_ao[MROWS * EE];
__device__ float  g_gq[MROWS];
__device__ float  g_gk[MROWS];

// ============================================================================
// helpers
// ============================================================================
__device__ __forceinline__ void mma_f16(float* d, const uint32_t* a, const uint32_t* b) {
    asm volatile(
        "mma.sync.aligned.m16n8k16.row.col.f32.f16.f16.f32 "
        "{%0,%1,%2,%3}, {%4,%5,%6,%7}, {%8,%9}, {%0,%1,%2,%3};"
        : "+f"(d[0]), "+f"(d[1]), "+f"(d[2]), "+f"(d[3])
        : "r"(a[0]), "r"(a[1]), "r"(a[2]), "r"(a[3]), "r"(b[0]), "r"(b[1]));
}
__device__ __forceinline__ uint32_t pack_h2(float lo, float hi) {
    __half2 h = __floats2half2_rn(lo, hi);
    return *(uint32_t*)&h;
}
__device__ __forceinline__ float rcpf(float x) {
    float r;
    asm("rcp.approx.f32 %0, %1;" : "=f"(r) : "f"(x));
    return r;
}
__device__ __forceinline__ float ex2f(float x) {
    float r;
    asm("ex2.approx.f32 %0, %1;" : "=f"(r) : "f"(x));
    return r;
}

// ---------------------------------------------------------------------------
// Weight transpose: W[k][n] fp32 -> g_wt[z][n][k] fp16. Tiled, coalesced.
// grid (16,16,4), block (32,8)
// ---------------------------------------------------------------------------
__global__ void transpose_w_kernel(
    const float* __restrict__ Wq, const float* __restrict__ Wk,
    const float* __restrict__ Wv, const float* __restrict__ Wo)
{
    __shared__ float t[32][33];
    const int z = blockIdx.z;
    const float* W = (z == 0) ? Wq : (z == 1) ? Wk : (z == 2) ? Wv : Wo;
    __half* out = g_wt + (size_t)z * EE * EE;
    const int x0 = blockIdx.x * 32, y0 = blockIdx.y * 32;
    const int tx = threadIdx.x, ty = threadIdx.y;
#pragma unroll
    for (int i = 0; i < 4; i++)
        t[ty + i * 8][tx] = W[(size_t)(y0 + ty + i * 8) * EE + x0 + tx];
    __syncthreads();
#pragma unroll
    for (int i = 0; i < 4; i++)
        out[(size_t)(x0 + ty + i * 8) * EE + y0 + tx] = __float2half_rn(t[tx][ty + i * 8]);
}

// ---------------------------------------------------------------------------
// FP16 GEMM body (m16n8k16, fp32 accum), software-pipelined double-buffered.
// C[M,512] = A[M,512] @ Bt^T + bias, Bt = [n][k] fp16.
// BM=128 BN=128 BK=16, 256 thr, warp tile 32x64.
// A: LDG fp32 -> cvt -> STS [m][k] halves (stride 24, conflict-free frags).
// B: cp.async direct from g_wt (no conversion).
// MODE 0: fp32 row-major out; MODE 1: fp16 row-major; MODE 2: fp16 transposed (g_vt16).
// ---------------------------------------------------------------------------
#define AKSTR 24
#define GA (128 * AKSTR)                 // halves per buffer
#define GEMM_SMEM (4 * GA * 2)           // 2 bufs x (A+B) halves -> 24576 bytes

template <int MODE>
__device__ __forceinline__ void gemm_body16(
    const float* __restrict__ A, const __half* __restrict__ Bt,
    const float* __restrict__ bias, void* __restrict__ Cout, int M,
    int row0, int col0, __half* sm)
{
    __half* Am = sm;                    // [2][128][24]
    __half* Bm = sm + 2 * GA;           // [2][128][24]

    const int tid = threadIdx.x;
    const int wid = tid >> 5, lane = tid & 31;
    const int g = lane >> 2, tg = lane & 3;
    const int wm = wid >> 1, wn = wid & 1;
    const int wrow = wm * 32, wcol = wn * 64;

    const int a_r0 = tid >> 2, a_c = (tid & 3) * 4;
    const int b_n = tid >> 1, b_s = (tid & 1) * 8;

    float acc[2][8][4];
#pragma unroll
    for (int mt = 0; mt < 2; mt++)
#pragma unroll
        for (int nt = 0; nt < 8; nt++)
#pragma unroll
            for (int e = 0; e < 4; e++) acc[mt][nt][e] = 0.f;

    float4 pa[2];

#define GA_LDG(K0)                                                             \
    {                                                                          \
        _Pragma("unroll")                                                      \
        for (int it = 0; it < 2; it++) {                                       \
            int r = a_r0 + it * 64;                                            \
            pa[it] = make_float4(0.f, 0.f, 0.f, 0.f);                          \
            if (row0 + r < M)                                                  \
                pa[it] = *(const float4*)&A[(size_t)(row0 + r) * 512 + (K0) + a_c]; \
        }                                                                      \
    }

#define GA_STS(Q)                                                             \
    {                                                                          \
        __half* am = Am + (Q) * GA;                                            \
        _Pragma("unroll")                                                      \
        for (int it = 0; it < 2; it++) {                                       \
            int r = a_r0 + it * 64;                                            \
            __half2 h01 = __floats2half2_rn(pa[it].x, pa[it].y);               \
            __half2 h23 = __floats2half2_rn(pa[it].z, pa[it].w);               \
            uint2 v;                                                           \
            v.x = *(uint32_t*)&h01;                                            \
            v.y = *(uint32_t*)&h23;                                            \
            *(uint2*)&am[r * AKSTR + a_c] = v;                                 \
        }                                                                      \
    }

#define GB_CP(K0, Q)                                                           \
    {                                                                          \
        __half* bm = Bm + (Q) * GA;                                            \
        __pipeline_memcpy_async(&bm[b_n * AKSTR + b_s],                        \
            Bt + (size_t)(col0 + b_n) * 512 + (K0) + b_s, 16, 0);              \
        __pipeline_commit();                                                   \
    }

    // prologue
    GB_CP(0, 0);
    GA_LDG(0);
    GA_STS(0);
    GA_LDG(16);
    __pipeline_wait_prior(0);
    __syncthreads();

    int p = 0;
    for (int k0 = 0; k0 < 512; k0 += 16) {
        if (k0 + 16 < 512) {
            GA_STS(1 - p);
            if (k0 + 32 < 512) GA_LDG(k0 + 32);
            GB_CP(k0 + 16, 1 - p);
        }

        const __half* am = Am + p * GA;
        const __half* bm = Bm + p * GA;
        uint32_t af[2][4];
#pragma unroll
        for (int mt = 0; mt < 2; mt++) {
            int r = wrow + mt * 16;
            af[mt][0] = *(const uint32_t*)&am[(r + g) * AKSTR + 2 * tg];
            af[mt][1] = *(const uint32_t*)&am[(r + g + 8) * AKSTR + 2 * tg];
            af[mt][2] = *(const uint32_t*)&am[(r + g) * AKSTR + 2 * tg + 8];
            af[mt][3] = *(const uint32_t*)&am[(r + g + 8) * AKSTR + 2 * tg + 8];
        }
        uint32_t bf[8][2];
#pragma unroll
        for (int nt = 0; nt < 8; nt++) {
            int c = wcol + nt * 8;
            bf[nt][0] = *(const uint32_t*)&bm[(c + g) * AKSTR + 2 * tg];
            bf[nt][1] = *(const uint32_t*)&bm[(c + g) * AKSTR + 2 * tg + 8];
        }
#pragma unroll
        for (int mt = 0; mt < 2; mt++)
#pragma unroll
            for (int nt = 0; nt < 8; nt++)
                mma_f16(acc[mt][nt], af[mt], bf[nt]);

        if (k0 + 16 < 512) {
            __pipeline_wait_prior(0);
            __syncthreads();
            p ^= 1;
        }
    }

#pragma unroll
    for (int mt = 0; mt < 2; mt++) {
        int r0 = row0 + wrow + mt * 16 + g;
#pragma unroll
        for (int nt = 0; nt < 8; nt++) {
            int c = col0 + wcol + nt * 8 + 2 * tg;
            float b0v = bias[c], b1v = bias[c + 1];
            float v00 = acc[mt][nt][0] + b0v, v01 = acc[mt][nt][1] + b1v;
            float v10 = acc[mt][nt][2] + b0v, v11 = acc[mt][nt][3] + b1v;
            if (MODE == 0) {
                float* C = (float*)Cout;
                if (r0 < M)
                    *(float2*)&C[(size_t)r0 * 512 + c] = make_float2(v00, v01);
                if (r0 + 8 < M)
                    *(float2*)&C[(size_t)(r0 + 8) * 512 + c] = make_float2(v10, v11);
            } else if (MODE == 1) {
                __half* C16 = (__half*)Cout;
                if (r0 < M)
                    *(__half2*)&C16[(size_t)r0 * 512 + c] = __floats2half2_rn(v00, v01);
                if (r0 + 8 < M)
                    *(__half2*)&C16[(size_t)(r0 + 8) * 512 + c] = __floats2half2_rn(v10, v11);
            } else {
                __half* C16 = (__half*)Cout;
                int hh = c >> 6, d = c & 63;
                size_t base = ((size_t)hh * 64 + d) * SSPH;
                if (r0 < M) {
                    int bi = (r0 >= SS) ? 1 : 0;
                    int s = r0 - bi * SS;
                    size_t o = (size_t)bi * HH * 64 * SSPH + base + s;
                    C16[o] = __float2half_rn(v00);
                    C16[o + SSPH] = __float2half_rn(v01);
                }
                if (r0 + 8 < M) {
                    int bi = (r0 + 8 >= SS) ? 1 : 0;
                    int s = r0 + 8 - bi * SS;
                    size_t o = (size_t)bi * HH * 64 * SSPH + base + s;
                    C16[o] = __float2half_rn(v10);
                    C16[o + SSPH] = __float2half_rn(v11);
                }
            }
        }
    }
#undef GA_LDG
#undef GA_STS
#undef GB_CP
}

__global__ __launch_bounds__(256, 2) void qkv_gemm_kernel(
    const float* __restrict__ A,
    const float* __restrict__ bq, const float* __restrict__ bk,
    const float* __restrict__ bv,
    void* Cq, void* Ck, void* Cv, int M)
{
    extern __shared__ __half hsm[];
    if (blockIdx.z == 0)
        gemm_body16<1>(A, g_wt, bq, Cq, M, blockIdx.y * 128, blockIdx.x * 128, hsm);
    else if (blockIdx.z == 1)
        gemm_body16<1>(A, g_wt + (size_t)EE * EE, bk, Ck, M, blockIdx.y * 128, blockIdx.x * 128, hsm);
    else
        gemm_body16<2>(A, g_wt + (size_t)2 * EE * EE, bv, Cv, M, blockIdx.y * 128, blockIdx.x * 128, hsm);
}

__global__ __launch_bounds__(256, 2) void out_gemm_kernel(
    const float* __restrict__ A, const float* __restrict__ bias,
    float* __restrict__ C, int M)
{
    extern __shared__ __half hsm[];
    gemm_body16<0>(A, g_wt + (size_t)3 * EE * EE, bias, C, M,
                   blockIdx.y * 128, blockIdx.x * 128, hsm);
}

// ---------------------------------------------------------------------------
// Gate dot products (reads fp16 q/k)
// ---------------------------------------------------------------------------
__global__ __launch_bounds__(128) void gate_kernel(const float* __restrict__ wg)
{
    const int row = blockIdx.x;
    const int tid = threadIdx.x;
    float sq = 0.f, sk = 0.f;
#pragma unroll
    for (int e = tid; e < 512; e += 128) {
        sq += __half2float(g_q16[(size_t)row * 512 + e]) * wg[e];
        sk += __half2float(g_k16[(size_t)row * 512 + e]) * wg[512 + e];
    }
#pragma unroll
    for (int off = 16; off >= 1; off >>= 1) {
        sq += __shfl_down_sync(0xffffffffu, sq, off);
        sk += __shfl_down_sync(0xffffffffu, sk, off);
    }
    __shared__ float pq[4], pk[4];
    if ((tid & 31) == 0) { pq[tid >> 5] = sq; pk[tid >> 5] = sk; }
    __syncthreads();
    if (tid == 0) {
        g_gq[row] = pq[0] + pq[1] + pq[2] + pq[3];
        g_gk[row] = pk[0] + pk[1] + pk[2] + pk[3];
    }
}

// ---------------------------------------------------------------------------
// FP16 mma.sync flash attention (m16n8k16, fp32 accum). Unchanged from R16.
// ---------------------------------------------------------------------------
#define HSTR 72
#define QBYTES (128 * HSTR * 2)
#define TBYTES (64 * HSTR * 2)
#define ATTN_SMEM (QBYTES + 4 * TBYTES + 512 + 64)

__global__ __launch_bounds__(256, 2) void attn_mma_kernel(const float* __restrict__ bg_ptr)
{
    extern __shared__ char smc[];
    __half* Qs   = (__half*)smc;
    __half* Kbuf = (__half*)(smc + QBYTES);
    __half* Vbuf = (__half*)(smc + QBYTES + 2 * TBYTES);
    float*  egk  = (float*)(smc + QBYTES + 4 * TBYTES);

    const int qb = blockIdx.x, h = blockIdx.y, b = blockIdx.z;
    const int q0 = qb * 128;
    const int tid = threadIdx.x;
    const int lane = tid & 31;
    const int g = lane >> 2, tg = lane & 3;
    const int wrow = (tid >> 5) * 16;
    const float bg = bg_ptr[0];

    const __half* qp16 = g_q16 + (size_t)(b * SS) * 512 + h * 64;
    const __half* kp16 = g_k16 + (size_t)(b * SS) * 512 + h * 64;
    const __half* vtp16 = g_vt16 + ((size_t)(b * HH + h)) * 64 * SSPH;

    int kstart = q0 - WINW; if (kstart < 0) kstart = 0;
    int kend = q0 + 128 + WINW; if (kend > SS) kend = SS;

#define STAGE_KV(K0, BBUF)                                                     \
    {                                                                          \
        __half* Kb = Kbuf + (BBUF) * (64 * HSTR);                              \
        __half* Vb = Vbuf + (BBUF) * (64 * HSTR);                              \
        int kr = tid >> 2;                                                     \
        int coff = (tid & 3) * 16;                                             \
        int gj = (K0) + kr;                                                    \
        int zfk = (gj < SS) ? 0 : 16;                                          \
        const __half* ksrc = kp16 + (size_t)gj * 512;                          \
        _Pragma("unroll")                                                      \
        for (int it = 0; it < 2; it++) {                                       \
            int c8 = coff + it * 8;                                            \
            __pipeline_memcpy_async(&Kb[kr * HSTR + c8], ksrc + c8, 16, zfk);  \
            int remv = SS - (K0) - c8;                                         \
            int zfv = (remv >= 8) ? 0 : ((remv > 0) ? (16 - 2 * remv) : 16);   \
            __pipeline_memcpy_async(&Vb[kr * HSTR + c8],                       \
                                    vtp16 + (size_t)kr * SSPH + (K0) + c8,     \
                                    16, zfv);                                  \
        }                                                                      \
        __pipeline_commit();                                                   \
    }

    STAGE_KV(kstart, 0);
    float gk_reg = 0.f;
    if (tid < 64) {
        int gj = kstart + tid;
        gk_reg = (gj < SS) ? g_gk[b * SS + gj] : 0.f;
    }
#pragma unroll
    for (int it = 0; it < 4; it++) {
        int idx = it * 256 + tid;
        int r = idx >> 3, c8 = (idx & 7) * 8;
        int gi = q0 + r;
        int zf = (gi < SS) ? 0 : 16;
        __pipeline_memcpy_async(&Qs[r * HSTR + c8],
                                qp16 + (size_t)gi * 512 + c8, 16, zf);
    }
    __pipeline_commit();

    if (tid < 64) {
        egk[tid] = __expf(-gk_reg - bg);
        if (kstart + 64 < kend) {
            int gj = kstart + 64 + tid;
            gk_reg = (gj < SS) ? g_gk[b * SS + gj] : 0.f;
        }
    }
    __pipeline_wait_prior(0);
    __syncthreads();

    uint32_t qa[4][4];
#pragma unroll
    for (int kc = 0; kc < 4; kc++) {
        qa[kc][0] = *(const uint32_t*)&Qs[(wrow + g) * HSTR + kc * 16 + 2 * tg];
        qa[kc][1] = *(const uint32_t*)&Qs[(wrow + g + 8) * HSTR + kc * 16 + 2 * tg];
        qa[kc][2] = *(const uint32_t*)&Qs[(wrow + g) * HSTR + kc * 16 + 2 * tg + 8];
        qa[kc][3] = *(const uint32_t*)&Qs[(wrow + g + 8) * HSTR + kc * 16 + 2 * tg + 8];
    }
    const int gi0 = q0 + wrow + g, gi1 = gi0 + 8;
    const float egq0 = __expf(-((gi0 < SS) ? g_gq[b * SS + gi0] : 0.f));
    const float egq1 = __expf(-((gi1 < SS) ? g_gq[b * SS + gi1] : 0.f));

    float oacc[8][4];
#pragma unroll
    for (int nt = 0; nt < 8; nt++)
#pragma unroll
        for (int e = 0; e < 4; e++) oacc[nt][e] = 0.f;
    float l0 = 0.f, l1 = 0.f;

    const float C1 = SCALE * LOG2E;
    const float C2 = BIASC * LOG2E;

    int p = 0;
    for (int k0 = kstart; k0 < kend; k0 += 64, p ^= 1) {
        __pipeline_wait_prior(0);
        __syncthreads();

        if (k0 + 64 < kend) {
            STAGE_KV(k0 + 64, 1 - p);
            if (tid < 64) {
                egk[(1 - p) * 64 + tid] = __expf(-gk_reg - bg);
                if (k0 + 128 < kend) {
                    int gj = k0 + 128 + tid;
                    gk_reg = (gj < SS) ? g_gk[b * SS + gj] : 0.f;
                }
            }
        }

        const __half* Kb = Kbuf + p * (64 * HSTR);
        const __half* Vb = Vbuf + p * (64 * HSTR);
        const float* eg_s = egk + p * 64;

        float sacc[8][4];
#pragma unroll
        for (int nt = 0; nt < 8; nt++)
#pragma unroll
            for (int e = 0; e < 4; e++) sacc[nt][e] = 0.f;
#pragma unroll
        for (int kc = 0; kc < 4; kc++) {
#pragma unroll
            for (int nt = 0; nt < 8; nt++) {
                uint32_t bf[2];
                bf[0] = *(const uint32_t*)&Kb[(nt * 8 + g) * HSTR + kc * 16 + 2 * tg];
                bf[1] = *(const uint32_t*)&Kb[(nt * 8 + g) * HSTR + kc * 16 + 2 * tg + 8];
                mma_f16(sacc[nt], qa[kc], bf);
            }
        }

        float lt0 = 0.f, lt1 = 0.f;
#pragma unroll
        for (int nt = 0; nt < 8; nt++) {
            int lj = nt * 8 + 2 * tg;
            float2 eg = *(float2*)&eg_s[lj];
            int gj0 = k0 + lj, gj1 = gj0 + 1;

            int d00 = gi0 - gj0, d01 = gi0 - gj1, d10 = gi1 - gj0, d11 = gi1 - gj1;
            {
                float gate = rcpf(fmaf(egq0, eg.x, 1.f));
                float pe = ex2f((sacc[nt][0] * C1 + (float)(d00 * d00) * C2) * gate);
                sacc[nt][0] = (gj0 < SS && d00 <= WINW && d00 >= -WINW) ? pe : 0.f;
            }
            {
                float gate = rcpf(fmaf(egq0, eg.y, 1.f));
                float pe = ex2f((sacc[nt][1] * C1 + (float)(d01 * d01) * C2) * gate);
                sacc[nt][1] = (gj1 < SS && d01 <= WINW && d01 >= -WINW) ? pe : 0.f;
            }
            {
                float gate = rcpf(fmaf(egq1, eg.x, 1.f));
                float pe = ex2f((sacc[nt][2] * C1 + (float)(d10 * d10) * C2) * gate);
                sacc[nt][2] = (gj0 < SS && d10 <= WINW && d10 >= -WINW) ? pe : 0.f;
            }
            {
                float gate = rcpf(fmaf(egq1, eg.y, 1.f));
                float pe = ex2f((sacc[nt][3] * C1 + (float)(d11 * d11) * C2) * gate);
                sacc[nt][3] = (gj1 < SS && d11 <= WINW && d11 >= -WINW) ? pe : 0.f;
            }
            lt0 += sacc[nt][0] + sacc[nt][1];
            lt1 += sacc[nt][2] + sacc[nt][3];
        }
        lt0 += __shfl_xor_sync(0xffffffffu, lt0, 1);
        lt0 += __shfl_xor_sync(0xffffffffu, lt0, 2);
        lt1 += __shfl_xor_sync(0xffffffffu, lt1, 1);
        lt1 += __shfl_xor_sync(0xffffffffu, lt1, 2);
        l0 += lt0;
        l1 += lt1;

#pragma unroll
        for (int kc = 0; kc < 4; kc++) {
            uint32_t pa[4];
            pa[0] = pack_h2(sacc[2 * kc][0],     sacc[2 * kc][1]);
            pa[1] = pack_h2(sacc[2 * kc][2],     sacc[2 * kc][3]);
            pa[2] = pack_h2(sacc[2 * kc + 1][0], sacc[2 * kc + 1][1]);
            pa[3] = pack_h2(sacc[2 * kc + 1][2], sacc[2 * kc + 1][3]);
#pragma unroll
            for (int nt = 0; nt < 8; nt++) {
                uint32_t bf[2];
                bf[0] = *(const uint32_t*)&Vb[(nt * 8 + g) * HSTR + kc * 16 + 2 * tg];
                bf[1] = *(const uint32_t*)&Vb[(nt * 8 + g) * HSTR + kc * 16 + 2 * tg + 8];
                mma_f16(oacc[nt], pa, bf);
            }
        }
    }

    const float inv0 = rcpf(l0), inv1 = rcpf(l1);
    float* op = g_ao + ((size_t)(b * SS)) * EE + h * 64;
#pragma unroll
    for (int nt = 0; nt < 8; nt++) {
        int c = nt * 8 + 2 * tg;
        if (gi0 < SS)
            *(float2*)&op[(size_t)gi0 * EE + c] =
                make_float2(oacc[nt][0] * inv0, oacc[nt][1] * inv0);
        if (gi1 < SS)
            *(float2*)&op[(size_t)gi1 * EE + c] =
                make_float2(oacc[nt][2] * inv1, oacc[nt][3] * inv1);
    }
#undef STAGE_KV
}

// ---------------------------------------------------------------------------
extern "C" void kernel_launch(void* const* d_in, const int* in_sizes, int n_in,
                              void* d_out, int out_size)
{
    const float* x  = (const float*)d_in[0];
    const float* Wq = (const float*)d_in[1];
    const float* bq = (const float*)d_in[2];
    const float* Wk = (const float*)d_in[3];
    const float* bk = (const float*)d_in[4];
    const float* Wv = (const float*)d_in[5];
    const float* bv = (const float*)d_in[6];
    const float* Wo = (const float*)d_in[7];
    const float* bo = (const float*)d_in[8];
    const float* wg = (const float*)d_in[9];
    const float* bg = (const float*)d_in[10];
    float* out = (float*)d_out;

    void *pq16, *pk16, *pvt16;
    float* pao;
    cudaGetSymbolAddress(&pq16, g_q16);
    cudaGetSymbolAddress(&pk16, g_k16);
    cudaGetSymbolAddress(&pvt16, g_vt16);
    cudaGetSymbolAddress((void**)&pao, g_ao);

    cudaFuncSetAttribute(attn_mma_kernel,
                         cudaFuncAttributeMaxDynamicSharedMemorySize, ATTN_SMEM);
    cudaFuncSetAttribute(qkv_gemm_kernel,
                         cudaFuncAttributeMaxDynamicSharedMemorySize, GEMM_SMEM);
    cudaFuncSetAttribute(out_gemm_kernel,
                         cudaFuncAttributeMaxDynamicSharedMemorySize, GEMM_SMEM);

    transpose_w_kernel<<<dim3(16, 16, 4), dim3(32, 8)>>>(Wq, Wk, Wv, Wo);
    dim3 gqkv(4, 33, 3);
    qkv_gemm_kernel<<<gqkv, 256, GEMM_SMEM>>>(x, bq, bk, bv, pq16, pk16, pvt16, MROWS);
    gate_kernel<<<MROWS, 128>>>(wg);
    attn_mma_kernel<<<dim3(17, HH, BB), 256, ATTN_SMEM>>>(bg);
    out_gemm_kernel<<<dim3(4, 33), 256, GEMM_SMEM>>>(pao, bo, out, MROWS);
}